// round 13
// baseline (speedup 1.0000x reference)
#include <cuda_runtime.h>

// EPN_layer: antisymmetric pairwise-MLP charge update.
// B=8, N=256, DH=32, DX=3, DQ=1, DE=8, H1=H2=32, DIN=80.
//
// Factorization (layer1 splits by input blocks):
//   A*[a] = inp_atom[a] @ W1[0:36] + b1,  Bt[a] = inp_atom[a] @ W1[36:72]
//   E[i,j] = e[i,j] @ W1[72:80]   (shared by both directions)
//   z1_ij = relu(A*_i + Bt_j + E), z1_ji = relu(A*_j + Bt_i + E); b3 cancels.
//
// R12 = R11 (persistent pair kernel, three-port weight split: W2-even/E-proj/
// b2/W3 on the constant port, W2-odd in smem, data streams in L1) with the
// prologue overhead removed:
//  * gather_weights + out-init FUSED into atom_proj (graph: 3 nodes, was 4;
//    the 4us gather launch disappears).
//  * pair row loop is SYNC-FREE: i-row A/B via uniform __ldg (no smem stage),
//    reduction via warp-shuffle + one atomicAdd per warp into out[bi]
//    (out pre-initialized to q in atom_proj). Block barrier only once,
//    after the one-time W2-odd staging.

#define BB 8
#define NN 256
#define H1C 32
#define H2C 32
#define DEC 8
#define NATOMS (BB * NN)   // 2048
#define PGRID 296          // persistent grid: 2 blocks x 148 SMs

// Per-atom projections packed by k-pair: g_AB4[kk*NATOMS+atom] =
//   (A[2kk], Bt[2kk], A[2kk+1], Bt[2kk+1])
__device__ float4 g_AB4[(H1C / 2) * NATOMS];

// Packed constant block (staged in g_stage by atom_proj, one memcpy to cAll):
//   [0,256)     W1 rows 72..79 (e-projection)    float4 idx: m*8+f4
//   [256,1280)  W2 [m][k]                        float4 idx: 64+m*8+t
//   [1280,1312) b2
//   [1312,1344) W3
#define CW2_F 256
#define CB2_F 1280
#define CW3_F 1312
#define CTOT  1344
__device__ alignas(16) float g_stage[CTOT];
__constant__ alignas(16) float cAll[CTOT];

typedef unsigned long long u64;

__device__ __forceinline__ u64 dup2(float w) {
    u64 r; asm("mov.b64 %0, {%1, %1};" : "=l"(r) : "f"(w)); return r;
}
__device__ __forceinline__ u64 pk2(float lo, float hi) {
    u64 r; asm("mov.b64 %0, {%1, %2};" : "=l"(r) : "f"(lo), "f"(hi)); return r;
}
__device__ __forceinline__ void upk2(float& lo, float& hi, u64 v) {
    asm("mov.b64 {%0, %1}, %2;" : "=f"(lo), "=f"(hi) : "l"(v));
}
__device__ __forceinline__ u64 fma2(u64 a, u64 b, u64 c) {
    u64 d; asm("fma.rn.f32x2 %0, %1, %2, %3;" : "=l"(d) : "l"(a), "l"(b), "l"(c));
    return d;
}
// float4 (in registers) viewed as two packed-f32x2 operands.
__device__ __forceinline__ ulonglong2 f4u2(float4 f) {
    ulonglong2 r; r.x = pk2(f.x, f.y); r.y = pk2(f.z, f.w); return r;
}

// ---------------------------------------------------------------------------
// Phase 0 (fused): per-atom projections + weight gather + out init.
// Thread id doubles as (atom, k-pair) index, staging index, and row index.
// ---------------------------------------------------------------------------
__global__ void atom_proj_kernel(const float* __restrict__ h,
                                 const float* __restrict__ x,
                                 const float* __restrict__ q,
                                 const float* __restrict__ W1,
                                 const float* __restrict__ b1,
                                 const float* __restrict__ W2,
                                 const float* __restrict__ b2,
                                 const float* __restrict__ W3,
                                 float* __restrict__ out)
{
    int id = blockIdx.x * blockDim.x + threadIdx.x;   // atom*16 + kk
    if (id >= NATOMS * (H1C / 2)) return;

    // side duties: weight staging and output init
    if (id < CTOT) {
        float v;
        if (id < CW2_F)      v = W1[72 * H1C + id];
        else if (id < CB2_F) v = W2[id - CW2_F];
        else if (id < CW3_F) v = b2[id - CB2_F];
        else                 v = W3[id - CW3_F];
        g_stage[id] = v;
    }
    if (id < NATOMS) out[id] = q[id];

    int kk   = id & 15;
    int atom = id >> 4;
    int k0 = 2 * kk, k1 = k0 + 1;

    float a0 = b1[k0], a1 = b1[k1];
    float t0 = 0.0f,   t1 = 0.0f;
    #pragma unroll
    for (int f = 0; f < 3; ++f) {
        float xv = x[atom * 3 + f];
        a0 = fmaf(xv, W1[f * H1C + k0],        a0);
        a1 = fmaf(xv, W1[f * H1C + k1],        a1);
        t0 = fmaf(xv, W1[(36 + f) * H1C + k0], t0);
        t1 = fmaf(xv, W1[(36 + f) * H1C + k1], t1);
    }
    #pragma unroll
    for (int f = 0; f < 32; ++f) {
        float hv = h[atom * 32 + f];
        a0 = fmaf(hv, W1[(3 + f) * H1C + k0],  a0);
        a1 = fmaf(hv, W1[(3 + f) * H1C + k1],  a1);
        t0 = fmaf(hv, W1[(39 + f) * H1C + k0], t0);
        t1 = fmaf(hv, W1[(39 + f) * H1C + k1], t1);
    }
    float qv = q[atom];
    a0 = fmaf(qv, W1[35 * H1C + k0], a0);
    a1 = fmaf(qv, W1[35 * H1C + k1], a1);
    t0 = fmaf(qv, W1[71 * H1C + k0], t0);
    t1 = fmaf(qv, W1[71 * H1C + k1], t1);

    g_AB4[kk * NATOMS + atom] = make_float4(a0, t0, a1, t1);
}

// ---------------------------------------------------------------------------
// Phase 1: persistent pair kernel. Block loops rows bi += PGRID; thread = j.
// Sync-free row loop; per-warp atomicAdd reduction into out.
// ---------------------------------------------------------------------------
__global__ __launch_bounds__(256, 2)
void pair_kernel(const float* __restrict__ e,
                 const float* __restrict__ mask,
                 float* __restrict__ out)
{
    __shared__ alignas(16) float sW2o[H1C / 2][H2C];  // odd-m rows of W2

    const int j = threadIdx.x;
    const float4* __restrict__ c4 = reinterpret_cast<const float4*>(cAll);

    // ---- one-time staging: odd W2 rows constant -> smem ----
    #pragma unroll
    for (int t = 0; t < 2; ++t) {
        int idx = threadIdx.x + t * 256;   // 512 = 16 rows x 32
        int mo = idx >> 5;                 // odd row m = 2*mo+1
        int k  = idx & 31;
        sW2o[mo][k] = cAll[CW2_F + (2 * mo + 1) * H2C + k];
    }
    __syncthreads();                        // only barrier in the kernel

    for (int bi = blockIdx.x; bi < NATOMS; bi += PGRID) {
        const int base = bi & ~(NN - 1);   // b*256

        // ---- per-pair inputs ----
        const float4* ep =
            reinterpret_cast<const float4*>(e + ((size_t)bi * NN + j) * DEC);
        float4 e0 = ep[0], e1 = ep[1];
        float ev[8] = {e0.x, e0.y, e0.z, e0.w, e1.x, e1.y, e1.z, e1.w};

        float emax = ev[0];
        #pragma unroll
        for (int m = 1; m < 8; ++m) emax = fmaxf(emax, ev[m]);
        const float mval  = mask[(size_t)bi * NN + j];
        const float scale = (emax > 1e-5f) ? 0.5f * mval : 0.0f;

        // ---- E = e @ W1c, packed over consecutive k-pairs (constant port) ----
        u64 Epk[H1C / 2];
        #pragma unroll
        for (int kk = 0; kk < 16; ++kk) Epk[kk] = 0ull;
        #pragma unroll
        for (int m = 0; m < 8; ++m) {
            u64 em2 = dup2(ev[m]);
            #pragma unroll
            for (int f4 = 0; f4 < 8; ++f4) {
                ulonglong2 w = f4u2(c4[m * 8 + f4]);     // LDC.128
                Epk[2 * f4]     = fma2(em2, w.x, Epk[2 * f4]);
                Epk[2 * f4 + 1] = fma2(em2, w.y, Epk[2 * f4 + 1]);
            }
        }

        // ---- z1 both directions (uniform i-row __ldg + coalesced j loads) ----
        float z_ij[H1C], z_ji[H1C];
        #pragma unroll
        for (int kk = 0; kk < 16; ++kk) {
            int k0 = 2 * kk, k1 = k0 + 1;
            float E0, E1; upk2(E0, E1, Epk[kk]);
            float4 abi = __ldg(&g_AB4[kk * NATOMS + bi]);        // uniform
            float4 abj = __ldg(&g_AB4[kk * NATOMS + base + j]);  // coalesced
            z_ij[k0] = fmaxf(abi.x + abj.y + E0, 0.0f);
            z_ji[k0] = fmaxf(abj.x + abi.y + E0, 0.0f);
            z_ij[k1] = fmaxf(abi.z + abj.w + E1, 0.0f);
            z_ji[k1] = fmaxf(abj.z + abi.w + E1, 0.0f);
        }

        // ---- layers 2+3: k in two halves; W2 even rows via constant port,
        //      odd rows via smem; chunk t covers floats m*32+half*16+4t..+3
        //      = k-pairs (2t, 2t+1) of this half. ----
        float s_ij = 0.0f, s_ji = 0.0f;
        #pragma unroll
        for (int half = 0; half < 2; ++half) {
            u64 accI[8], accJ[8];
            #pragma unroll
            for (int kk = 0; kk < 8; ++kk) {
                int k0 = half * 16 + 2 * kk;
                u64 bv = pk2(cAll[CB2_F + k0], cAll[CB2_F + k0 + 1]);
                accI[kk] = bv; accJ[kk] = bv;
            }

            #pragma unroll
            for (int m = 0; m < H1C; ++m) {
                u64 zi2 = dup2(z_ij[m]);
                u64 zj2 = dup2(z_ji[m]);
                ulonglong2 w0, w1, w2, w3;   // 4 x (2 k-pairs each)
                if (m & 1) {
                    const ulonglong2* wr = reinterpret_cast<const ulonglong2*>(
                        &sW2o[m >> 1][half * 16]);
                    w0 = wr[0]; w1 = wr[1]; w2 = wr[2]; w3 = wr[3];  // LDS.128
                } else {
                    w0 = f4u2(c4[64 + m * 8 + half * 4 + 0]);        // LDC.128
                    w1 = f4u2(c4[64 + m * 8 + half * 4 + 1]);
                    w2 = f4u2(c4[64 + m * 8 + half * 4 + 2]);
                    w3 = f4u2(c4[64 + m * 8 + half * 4 + 3]);
                }
                accI[0] = fma2(zi2, w0.x, accI[0]);
                accJ[0] = fma2(zj2, w0.x, accJ[0]);
                accI[1] = fma2(zi2, w0.y, accI[1]);
                accJ[1] = fma2(zj2, w0.y, accJ[1]);
                accI[2] = fma2(zi2, w1.x, accI[2]);
                accJ[2] = fma2(zj2, w1.x, accJ[2]);
                accI[3] = fma2(zi2, w1.y, accI[3]);
                accJ[3] = fma2(zj2, w1.y, accJ[3]);
                accI[4] = fma2(zi2, w2.x, accI[4]);
                accJ[4] = fma2(zj2, w2.x, accJ[4]);
                accI[5] = fma2(zi2, w2.y, accI[5]);
                accJ[5] = fma2(zj2, w2.y, accJ[5]);
                accI[6] = fma2(zi2, w3.x, accI[6]);
                accJ[6] = fma2(zj2, w3.x, accJ[6]);
                accI[7] = fma2(zi2, w3.y, accI[7]);
                accJ[7] = fma2(zj2, w3.y, accJ[7]);
            }

            #pragma unroll
            for (int kk = 0; kk < 8; ++kk) {
                int k0 = half * 16 + 2 * kk;
                float w0 = cAll[CW3_F + k0], w1 = cAll[CW3_F + k0 + 1];
                float a, b;
                upk2(a, b, accI[kk]);
                s_ij = fmaf(fmaxf(a, 0.0f), w0, s_ij);
                s_ij = fmaf(fmaxf(b, 0.0f), w1, s_ij);
                upk2(a, b, accJ[kk]);
                s_ji = fmaf(fmaxf(a, 0.0f), w0, s_ji);
                s_ji = fmaf(fmaxf(b, 0.0f), w1, s_ji);
            }
        }
        float val = scale * (s_ij - s_ji);   // b3 cancels

        // ---- warp reduction + one atomicAdd per warp (out pre-init to q) ----
        #pragma unroll
        for (int off = 16; off > 0; off >>= 1)
            val += __shfl_xor_sync(0xffffffffu, val, off);
        if ((threadIdx.x & 31) == 0)
            atomicAdd(&out[bi], val);
    }
}

// ---------------------------------------------------------------------------
// Launch. Inputs (metadata order): h, e, x, q, mask, W1, b1, W2, b2, W3, b3.
// Graph: atom_proj(fused gather/init) -> memcpy(cAll) -> pair  (3 nodes).
// ---------------------------------------------------------------------------
extern "C" void kernel_launch(void* const* d_in, const int* in_sizes, int n_in,
                              void* d_out, int out_size)
{
    const float* h    = (const float*)d_in[0];
    const float* e    = (const float*)d_in[1];
    const float* x    = (const float*)d_in[2];
    const float* q    = (const float*)d_in[3];
    const float* mask = (const float*)d_in[4];
    const float* W1   = (const float*)d_in[5];
    const float* b1   = (const float*)d_in[6];
    const float* W2   = (const float*)d_in[7];
    const float* b2   = (const float*)d_in[8];
    const float* W3   = (const float*)d_in[9];
    // d_in[10] = b3: cancels in elec_ij - elec_ji.
    float* out = (float*)d_out;

    atom_proj_kernel<<<(NATOMS * (H1C / 2) + 255) / 256, 256>>>(
        h, x, q, W1, b1, W2, b2, W3, out);

    void *pAll, *pStage;
    cudaGetSymbolAddress(&pAll,   cAll);
    cudaGetSymbolAddress(&pStage, g_stage);
    cudaMemcpyAsync(pAll, pStage, CTOT * sizeof(float), cudaMemcpyDeviceToDevice);

    pair_kernel<<<PGRID, 256>>>(e, mask, out);
}

// round 15
// speedup vs baseline: 1.2206x; 1.2206x over previous
#include <cuda_runtime.h>

// EPN_layer: antisymmetric pairwise-MLP charge update.
// B=8, N=256, DH=32, DX=3, DQ=1, DE=8, H1=H2=32, DIN=80.
//
// Factorization (layer1 splits by input blocks):
//   A*[a] = inp_atom[a] @ W1[0:36] + b1,  Bt[a] = inp_atom[a] @ W1[36:72]
//   E[i,j] = e[i,j] @ W1[72:80]   (shared by both directions)
//   z1_ij = relu(A*_i + Bt_j + E), z1_ji = relu(A*_j + Bt_i + E); b3 cancels.
//
// R14 = resubmission of R13 (round failed on container infra, not kernel):
//  * pair row loop = R11's proven form (per-row sAi/sBi SMEM staging + syncs
//    + sred reduction; i-row data via LDS broadcast, NOT uniform LDG — the
//    uniform-LDG z-path was the R12 regression, same failure mode as R6).
//  * prologue = R12's fused atom_proj (weight gather fused in; graph is
//    atom_proj -> memcpy(cAll) -> pair, 3 nodes, no 4us gather launch).
//  * three-port weight split unchanged: W2-even/E-proj/b2/W3 on the constant
//    port (LDC.128), W2-odd rows in smem (LDS.128), data streams in L1.

#define BB 8
#define NN 256
#define H1C 32
#define H2C 32
#define DEC 8
#define NATOMS (BB * NN)   // 2048
#define PGRID 296          // persistent grid: 2 blocks x 148 SMs

// Per-atom projections packed by k-pair: g_AB4[kk*NATOMS+atom] =
//   (A[2kk], Bt[2kk], A[2kk+1], Bt[2kk+1])
__device__ float4 g_AB4[(H1C / 2) * NATOMS];

// Packed constant block (staged in g_stage by atom_proj, one memcpy to cAll):
//   [0,256)     W1 rows 72..79 (e-projection)    float4 idx: m*8+f4
//   [256,1280)  W2 [m][k]                        float4 idx: 64+m*8+t
//   [1280,1312) b2
//   [1312,1344) W3
#define CW2_F 256
#define CB2_F 1280
#define CW3_F 1312
#define CTOT  1344
__device__ alignas(16) float g_stage[CTOT];
__constant__ alignas(16) float cAll[CTOT];

typedef unsigned long long u64;

__device__ __forceinline__ u64 dup2(float w) {
    u64 r; asm("mov.b64 %0, {%1, %1};" : "=l"(r) : "f"(w)); return r;
}
__device__ __forceinline__ u64 pk2(float lo, float hi) {
    u64 r; asm("mov.b64 %0, {%1, %2};" : "=l"(r) : "f"(lo), "f"(hi)); return r;
}
__device__ __forceinline__ void upk2(float& lo, float& hi, u64 v) {
    asm("mov.b64 {%0, %1}, %2;" : "=f"(lo), "=f"(hi) : "l"(v));
}
__device__ __forceinline__ u64 fma2(u64 a, u64 b, u64 c) {
    u64 d; asm("fma.rn.f32x2 %0, %1, %2, %3;" : "=l"(d) : "l"(a), "l"(b), "l"(c));
    return d;
}
// float4 (in registers) viewed as two packed-f32x2 operands.
__device__ __forceinline__ ulonglong2 f4u2(float4 f) {
    ulonglong2 r; r.x = pk2(f.x, f.y); r.y = pk2(f.z, f.w); return r;
}

// ---------------------------------------------------------------------------
// Phase 0 (fused): per-atom projections + weight gather.
// ---------------------------------------------------------------------------
__global__ void atom_proj_kernel(const float* __restrict__ h,
                                 const float* __restrict__ x,
                                 const float* __restrict__ q,
                                 const float* __restrict__ W1,
                                 const float* __restrict__ b1,
                                 const float* __restrict__ W2,
                                 const float* __restrict__ b2,
                                 const float* __restrict__ W3)
{
    int id = blockIdx.x * blockDim.x + threadIdx.x;   // atom*16 + kk
    if (id >= NATOMS * (H1C / 2)) return;

    // side duty: weight staging into g_stage
    if (id < CTOT) {
        float v;
        if (id < CW2_F)      v = W1[72 * H1C + id];
        else if (id < CB2_F) v = W2[id - CW2_F];
        else if (id < CW3_F) v = b2[id - CB2_F];
        else                 v = W3[id - CW3_F];
        g_stage[id] = v;
    }

    int kk   = id & 15;
    int atom = id >> 4;
    int k0 = 2 * kk, k1 = k0 + 1;

    float a0 = b1[k0], a1 = b1[k1];
    float t0 = 0.0f,   t1 = 0.0f;
    #pragma unroll
    for (int f = 0; f < 3; ++f) {
        float xv = x[atom * 3 + f];
        a0 = fmaf(xv, W1[f * H1C + k0],        a0);
        a1 = fmaf(xv, W1[f * H1C + k1],        a1);
        t0 = fmaf(xv, W1[(36 + f) * H1C + k0], t0);
        t1 = fmaf(xv, W1[(36 + f) * H1C + k1], t1);
    }
    #pragma unroll
    for (int f = 0; f < 32; ++f) {
        float hv = h[atom * 32 + f];
        a0 = fmaf(hv, W1[(3 + f) * H1C + k0],  a0);
        a1 = fmaf(hv, W1[(3 + f) * H1C + k1],  a1);
        t0 = fmaf(hv, W1[(39 + f) * H1C + k0], t0);
        t1 = fmaf(hv, W1[(39 + f) * H1C + k1], t1);
    }
    float qv = q[atom];
    a0 = fmaf(qv, W1[35 * H1C + k0], a0);
    a1 = fmaf(qv, W1[35 * H1C + k1], a1);
    t0 = fmaf(qv, W1[71 * H1C + k0], t0);
    t1 = fmaf(qv, W1[71 * H1C + k1], t1);

    g_AB4[kk * NATOMS + atom] = make_float4(a0, t0, a1, t1);
}

// ---------------------------------------------------------------------------
// Phase 1: persistent pair kernel. Block loops rows bi += PGRID; thread = j.
// Per-row i-row staging in smem (LDS broadcast), sred block reduction.
// ---------------------------------------------------------------------------
__global__ __launch_bounds__(256, 2)
void pair_kernel(const float* __restrict__ e,
                 const float* __restrict__ mask,
                 const float* __restrict__ q,
                 float* __restrict__ out)
{
    __shared__ alignas(16) float sW2o[H1C / 2][H2C];  // odd-m rows of W2
    __shared__ float sAi[H1C];
    __shared__ float sBi[H1C];
    __shared__ float sred[8];

    const int j = threadIdx.x;
    const float4* __restrict__ c4 = reinterpret_cast<const float4*>(cAll);

    // ---- one-time staging: odd W2 rows constant -> smem ----
    #pragma unroll
    for (int t = 0; t < 2; ++t) {
        int idx = threadIdx.x + t * 256;   // 512 = 16 rows x 32
        int mo = idx >> 5;                 // odd row m = 2*mo+1
        int k  = idx & 31;
        sW2o[mo][k] = cAll[CW2_F + (2 * mo + 1) * H2C + k];
    }

    for (int bi = blockIdx.x; bi < NATOMS; bi += PGRID) {
        const int base = bi & ~(NN - 1);   // b*256

        // per-row staging: i-row A/B into smem (first iter shares this sync
        // with the W2-odd staging above)
        if (threadIdx.x < H1C / 2) {
            float4 f0 = g_AB4[threadIdx.x * NATOMS + bi];
            sAi[2 * threadIdx.x]     = f0.x;
            sBi[2 * threadIdx.x]     = f0.y;
            sAi[2 * threadIdx.x + 1] = f0.z;
            sBi[2 * threadIdx.x + 1] = f0.w;
        }
        __syncthreads();

        // ---- per-pair inputs ----
        const float4* ep =
            reinterpret_cast<const float4*>(e + ((size_t)bi * NN + j) * DEC);
        float4 e0 = ep[0], e1 = ep[1];
        float ev[8] = {e0.x, e0.y, e0.z, e0.w, e1.x, e1.y, e1.z, e1.w};

        float emax = ev[0];
        #pragma unroll
        for (int m = 1; m < 8; ++m) emax = fmaxf(emax, ev[m]);
        const float mval  = mask[(size_t)bi * NN + j];
        const float scale = (emax > 1e-5f) ? 0.5f * mval : 0.0f;

        // ---- E = e @ W1c, packed over consecutive k-pairs (constant port) ----
        u64 Epk[H1C / 2];
        #pragma unroll
        for (int kk = 0; kk < 16; ++kk) Epk[kk] = 0ull;
        #pragma unroll
        for (int m = 0; m < 8; ++m) {
            u64 em2 = dup2(ev[m]);
            #pragma unroll
            for (int f4 = 0; f4 < 8; ++f4) {
                ulonglong2 w = f4u2(c4[m * 8 + f4]);     // LDC.128
                Epk[2 * f4]     = fma2(em2, w.x, Epk[2 * f4]);
                Epk[2 * f4 + 1] = fma2(em2, w.y, Epk[2 * f4 + 1]);
            }
        }

        // ---- z1 both directions (smem i-row + coalesced float4 j loads) ----
        float z_ij[H1C], z_ji[H1C];
        #pragma unroll
        for (int kk = 0; kk < 16; ++kk) {
            int k0 = 2 * kk, k1 = k0 + 1;
            float E0, E1; upk2(E0, E1, Epk[kk]);
            float4 ab = __ldg(&g_AB4[kk * NATOMS + base + j]);   // coalesced
            z_ij[k0] = fmaxf(sAi[k0] + ab.y + E0, 0.0f);
            z_ji[k0] = fmaxf(ab.x + sBi[k0] + E0, 0.0f);
            z_ij[k1] = fmaxf(sAi[k1] + ab.w + E1, 0.0f);
            z_ji[k1] = fmaxf(ab.z + sBi[k1] + E1, 0.0f);
        }

        // ---- layers 2+3: k in two halves; W2 even rows via constant port,
        //      odd rows via smem; chunk t covers floats m*32+half*16+4t..+3
        //      = k-pairs (2t, 2t+1) of this half. ----
        float s_ij = 0.0f, s_ji = 0.0f;
        #pragma unroll
        for (int half = 0; half < 2; ++half) {
            u64 accI[8], accJ[8];
            #pragma unroll
            for (int kk = 0; kk < 8; ++kk) {
                int k0 = half * 16 + 2 * kk;
                u64 bv = pk2(cAll[CB2_F + k0], cAll[CB2_F + k0 + 1]);
                accI[kk] = bv; accJ[kk] = bv;
            }

            #pragma unroll
            for (int m = 0; m < H1C; ++m) {
                u64 zi2 = dup2(z_ij[m]);
                u64 zj2 = dup2(z_ji[m]);
                ulonglong2 w0, w1, w2, w3;   // 4 x (2 k-pairs each)
                if (m & 1) {
                    const ulonglong2* wr = reinterpret_cast<const ulonglong2*>(
                        &sW2o[m >> 1][half * 16]);
                    w0 = wr[0]; w1 = wr[1]; w2 = wr[2]; w3 = wr[3];  // LDS.128
                } else {
                    w0 = f4u2(c4[64 + m * 8 + half * 4 + 0]);        // LDC.128
                    w1 = f4u2(c4[64 + m * 8 + half * 4 + 1]);
                    w2 = f4u2(c4[64 + m * 8 + half * 4 + 2]);
                    w3 = f4u2(c4[64 + m * 8 + half * 4 + 3]);
                }
                accI[0] = fma2(zi2, w0.x, accI[0]);
                accJ[0] = fma2(zj2, w0.x, accJ[0]);
                accI[1] = fma2(zi2, w0.y, accI[1]);
                accJ[1] = fma2(zj2, w0.y, accJ[1]);
                accI[2] = fma2(zi2, w1.x, accI[2]);
                accJ[2] = fma2(zj2, w1.x, accJ[2]);
                accI[3] = fma2(zi2, w1.y, accI[3]);
                accJ[3] = fma2(zj2, w1.y, accJ[3]);
                accI[4] = fma2(zi2, w2.x, accI[4]);
                accJ[4] = fma2(zj2, w2.x, accJ[4]);
                accI[5] = fma2(zi2, w2.y, accI[5]);
                accJ[5] = fma2(zj2, w2.y, accJ[5]);
                accI[6] = fma2(zi2, w3.x, accI[6]);
                accJ[6] = fma2(zj2, w3.x, accJ[6]);
                accI[7] = fma2(zi2, w3.y, accI[7]);
                accJ[7] = fma2(zj2, w3.y, accJ[7]);
            }

            #pragma unroll
            for (int kk = 0; kk < 8; ++kk) {
                int k0 = half * 16 + 2 * kk;
                float w0 = cAll[CW3_F + k0], w1 = cAll[CW3_F + k0 + 1];
                float a, b;
                upk2(a, b, accI[kk]);
                s_ij = fmaf(fmaxf(a, 0.0f), w0, s_ij);
                s_ij = fmaf(fmaxf(b, 0.0f), w1, s_ij);
                upk2(a, b, accJ[kk]);
                s_ji = fmaf(fmaxf(a, 0.0f), w0, s_ji);
                s_ji = fmaf(fmaxf(b, 0.0f), w1, s_ji);
            }
        }
        float val = scale * (s_ij - s_ji);   // b3 cancels

        // ---- block reduction over j ----
        #pragma unroll
        for (int off = 16; off > 0; off >>= 1)
            val += __shfl_xor_sync(0xffffffffu, val, off);
        if ((threadIdx.x & 31) == 0) sred[threadIdx.x >> 5] = val;
        __syncthreads();
        if (threadIdx.x == 0) {
            float t = 0.0f;
            #pragma unroll
            for (int w = 0; w < 8; ++w) t += sred[w];
            out[bi] = q[bi] + t;
        }
        // next iteration's sAi/sred writes are guarded by its leading sync
    }
}

// ---------------------------------------------------------------------------
// Launch. Inputs (metadata order): h, e, x, q, mask, W1, b1, W2, b2, W3, b3.
// Graph: atom_proj(fused gather) -> memcpy(cAll) -> pair  (3 nodes).
// ---------------------------------------------------------------------------
extern "C" void kernel_launch(void* const* d_in, const int* in_sizes, int n_in,
                              void* d_out, int out_size)
{
    const float* h    = (const float*)d_in[0];
    const float* e    = (const float*)d_in[1];
    const float* x    = (const float*)d_in[2];
    const float* q    = (const float*)d_in[3];
    const float* mask = (const float*)d_in[4];
    const float* W1   = (const float*)d_in[5];
    const float* b1   = (const float*)d_in[6];
    const float* W2   = (const float*)d_in[7];
    const float* b2   = (const float*)d_in[8];
    const float* W3   = (const float*)d_in[9];
    // d_in[10] = b3: cancels in elec_ij - elec_ji.
    float* out = (float*)d_out;

    atom_proj_kernel<<<(NATOMS * (H1C / 2) + 255) / 256, 256>>>(
        h, x, q, W1, b1, W2, b2, W3);

    void *pAll, *pStage;
    cudaGetSymbolAddress(&pAll,   cAll);
    cudaGetSymbolAddress(&pStage, g_stage);
    cudaMemcpyAsync(pAll, pStage, CTOT * sizeof(float), cudaMemcpyDeviceToDevice);

    pair_kernel<<<PGRID, 256>>>(e, mask, q, out);
}